// round 8
// baseline (speedup 1.0000x reference)
#include <cuda_runtime.h>
#include <cuda_bf16.h>
#include <cstdint>

typedef __nv_bfloat16 bf16;

#define WSZ (512*512)
#define XSZ (8*512*512)
#define FIXCAP (1<<20)

// ---------------- device scratch ----------------
__device__ bf16     g_wsp[4][2][WSZ];   // weight splits (2 levels)
__device__ bf16     g_xT[2][XSZ];       // x^T splits [b][n][c]
__device__ bf16     g_yT[2][XSZ];       // y^T splits
__device__ float    g_xTf[XSZ];         // x^T fp32 [b][n][c] (for coalesced fixup)
__device__ float    g_yTf[XSZ];         // y^T fp32
__device__ uint8_t  g_q[XSZ], g_k[XSZ], g_v[XSZ];
__device__ bf16     g_sT[XSZ];          // attn spikes^T bf16 [b][n][c]
__device__ int      g_cnt[2];
__device__ uint32_t g_fix[2][FIXCAP];

// ---------------- PTX helpers (arch-generic, sm_80+) ----------------
__device__ __forceinline__ uint32_t smem_u32(const void* p) {
    uint32_t a;
    asm("{ .reg .u64 t; cvta.to.shared.u64 t, %1; cvt.u32.u64 %0, t; }" : "=r"(a) : "l"(p));
    return a;
}
__device__ __forceinline__ void cp16(uint32_t dst, const void* src) {
    asm volatile("cp.async.cg.shared.global [%0], [%1], 16;" :: "r"(dst), "l"(src) : "memory");
}
__device__ __forceinline__ void cp_commit() { asm volatile("cp.async.commit_group;" ::: "memory"); }
template<int N> __device__ __forceinline__ void cp_wait() {
    asm volatile("cp.async.wait_group %0;" :: "n"(N) : "memory");
}
__device__ __forceinline__ void ldmx4(uint32_t& r0, uint32_t& r1, uint32_t& r2, uint32_t& r3, uint32_t a) {
    asm volatile("ldmatrix.sync.aligned.m8n8.x4.shared.b16 {%0,%1,%2,%3}, [%4];"
                 : "=r"(r0), "=r"(r1), "=r"(r2), "=r"(r3) : "r"(a));
}
__device__ __forceinline__ void mma_bf16(float& c0, float& c1, float& c2, float& c3,
                                         uint32_t a0, uint32_t a1, uint32_t a2, uint32_t a3,
                                         uint32_t b0, uint32_t b1) {
    asm volatile("mma.sync.aligned.m16n8k16.row.col.f32.bf16.bf16.f32 "
                 "{%0,%1,%2,%3}, {%4,%5,%6,%7}, {%8,%9}, {%0,%1,%2,%3};"
                 : "+f"(c0), "+f"(c1), "+f"(c2), "+f"(c3)
                 : "r"(a0), "r"(a1), "r"(a2), "r"(a3), "r"(b0), "r"(b1));
}

// 2-way bf16 split (truncation): w ≈ h + l, residual ~2^-16 relative
__device__ __forceinline__ void split2(float w, bf16& h, bf16& l) {
    h = __float2bfloat16_rz(w);
    l = __float2bfloat16_rz(w - __bfloat162float(h));
}

// ---------------- prep kernels ----------------
__global__ void prep_split4(const float* __restrict__ w0, const float* __restrict__ w1,
                            const float* __restrict__ w2, const float* __restrict__ w3,
                            bf16* __restrict__ dst) {
    if (blockIdx.x == 0 && blockIdx.y == 0 && threadIdx.x == 0) { g_cnt[0] = 0; g_cnt[1] = 0; }
    const float* ws[4] = {w0, w1, w2, w3};
    const int wi = blockIdx.y;
    const float* w = ws[wi];
    bf16* h = dst + (size_t)(wi * 2 + 0) * WSZ;
    bf16* l = dst + (size_t)(wi * 2 + 1) * WSZ;
    for (int i = blockIdx.x * 256 + threadIdx.x; i < WSZ; i += gridDim.x * 256) {
        bf16 a, b;
        split2(w[i], a, b);
        h[i] = a; l[i] = b;
    }
}

// transpose [b][c][n] -> [b][n][c]: 2-way bf16 split + fp32 copy
__global__ void prep_xyT(const float* __restrict__ x, const float* __restrict__ y,
                         bf16* __restrict__ xT, bf16* __restrict__ yT,
                         float* __restrict__ xTf, float* __restrict__ yTf) {
    __shared__ float t[32][33];
    const int z = blockIdx.z;
    const int b = z & 7;
    const float* src0 = (z < 8) ? x : y;
    bf16* d0 = (z < 8) ? xT : yT;
    float* df = (z < 8) ? xTf : yTf;
    const int c0 = blockIdx.y * 32, n0 = blockIdx.x * 32;
    const int r = threadIdx.x >> 5, j = threadIdx.x & 31;
    const float* src = src0 + ((size_t)b * 512 + c0) * 512 + n0;
#pragma unroll
    for (int i = r; i < 32; i += 8) t[i][j] = src[(size_t)i * 512 + j];
    __syncthreads();
    const size_t dst = ((size_t)b * 512 + n0) * 512 + c0;
#pragma unroll
    for (int i = r; i < 32; i += 8) {
        const float v = t[j][i];
        bf16 a, bb;
        split2(v, a, bb);
        d0[0 * (size_t)XSZ + dst + (size_t)i * 512 + j] = a;
        d0[1 * (size_t)XSZ + dst + (size_t)i * 512 + j] = bb;
        df[dst + (size_t)i * 512 + j] = v;
    }
}

// ---------------- bf16 mma GEMM + BN + LIF (+ borderline flagging) ----------------
// D = A0*B0 + A0*B1 + A1*B0 (NB=2)  or  A0*B0 + A1*B0 (NB=1)
// 128x128 tile, BK=64, 8 stages, double-buffered cp.async, 256 threads (2x4 warps).
template<int NB, bool OUT_U8>
__device__ __forceinline__ void gemm_body(const bf16* __restrict__ A0, const bf16* __restrict__ A1,
                                          const bf16* __restrict__ B0, const bf16* __restrict__ B1,
                                          void* Out,
                                          const float* __restrict__ gam, const float* __restrict__ bet,
                                          const float* __restrict__ mean, const float* __restrict__ var,
                                          int bz, int stage, int which, char* sm) {
    const int NT = 2 + NB;                 // tiles per stage
    const int tid = threadIdx.x;
    const int lane = tid & 31, wid = tid >> 5;
    const int warp_m = wid & 1, warp_n = wid >> 1;
    const int row0 = blockIdx.y * 128, col0 = blockIdx.x * 128;
    const uint32_t sbase = smem_u32(sm);

    float acc[4][4][4];
#pragma unroll
    for (int i = 0; i < 4; i++)
#pragma unroll
        for (int j = 0; j < 4; j++)
#pragma unroll
            for (int q = 0; q < 4; q++) acc[i][j][q] = 0.0f;

    const bf16* srcs[4];
    srcs[0] = A0 + (size_t)row0 * 512;
    srcs[1] = A1 + (size_t)row0 * 512;
    srcs[2] = B0 + ((size_t)bz * 512 + col0) * 512;
    if (NB == 2) srcs[3] = B1 + ((size_t)bz * 512 + col0) * 512;

    // stage = NT tiles of [128][64] bf16; tile chunk (r, c): 16B at row r, chunk c^(r&7)
    auto issue = [&](int kt, int stg) {
        const uint32_t sb = sbase + stg * NT * 16384;
#pragma unroll
        for (int t = 0; t < NT; t++) {
            const bf16* base = srcs[t] + (kt << 6);
#pragma unroll
            for (int i = 0; i < 4; i++) {
                const int idx = tid + i * 256;
                const int r = idx >> 3, c = idx & 7;
                const uint32_t off = r * 128 + ((c ^ (r & 7)) << 4);
                cp16(sb + t * 16384 + off, base + (size_t)r * 512 + c * 8);
            }
        }
        cp_commit();
    };

    auto ldA = [&](uint32_t Af[4][4], uint32_t sA, int ks) {
#pragma unroll
        for (int tm = 0; tm < 4; tm++) {
            const int r = warp_m * 64 + tm * 16 + (lane & 15);
            const int ch = ks * 2 + (lane >> 4);
            ldmx4(Af[tm][0], Af[tm][1], Af[tm][2], Af[tm][3],
                  sA + r * 128 + ((ch ^ (r & 7)) << 4));
        }
    };
    auto ldB = [&](uint32_t Bf[2][4], uint32_t sB, int ks) {
#pragma unroll
        for (int tp = 0; tp < 2; tp++) {
            const int r = warp_n * 32 + tp * 16 + (lane & 7) + ((lane & 16) >> 1);
            const int ch = ks * 2 + ((lane >> 3) & 1);
            ldmx4(Bf[tp][0], Bf[tp][1], Bf[tp][2], Bf[tp][3],
                  sB + r * 128 + ((ch ^ (r & 7)) << 4));
        }
    };
    auto pass = [&](uint32_t Af[4][4], uint32_t Bf[2][4]) {
#pragma unroll
        for (int tm = 0; tm < 4; tm++)
#pragma unroll
            for (int tn = 0; tn < 4; tn++)
                mma_bf16(acc[tm][tn][0], acc[tm][tn][1], acc[tm][tn][2], acc[tm][tn][3],
                         Af[tm][0], Af[tm][1], Af[tm][2], Af[tm][3],
                         Bf[tn >> 1][(tn & 1) * 2], Bf[tn >> 1][(tn & 1) * 2 + 1]);
    };

    auto compute = [&](int stg) {
        const uint32_t sb = sbase + stg * NT * 16384;
#pragma unroll
        for (int ks = 0; ks < 4; ks++) {
            uint32_t Af0[4][4], Af1[4][4], Bf0[2][4];
            ldA(Af0, sb, ks);
            ldB(Bf0, sb + 2 * 16384, ks);
            ldA(Af1, sb + 16384, ks);
            if (NB == 2) {
                uint32_t Bf1[2][4];
                ldB(Bf1, sb + 3 * 16384, ks);
                pass(Af0, Bf0);
                pass(Af0, Bf1);
                pass(Af1, Bf0);
            } else {
                pass(Af0, Bf0);
                pass(Af1, Bf0);
            }
        }
    };

    issue(0, 0);
    for (int kt = 0; kt < 8; kt++) {
        if (kt + 1 < 8) { issue(kt + 1, (kt + 1) & 1); cp_wait<1>(); }
        else cp_wait<0>();
        __syncthreads();
        compute(kt & 1);
        __syncthreads();
    }

    // ---- epilogue: BN + LIF; flag borderline values for exact fp64 fixup ----
    const int r0l = lane >> 2, c0l = (lane & 3) * 2;
#pragma unroll
    for (int tm = 0; tm < 4; tm++) {
#pragma unroll
        for (int half = 0; half < 2; half++) {
            const int m = row0 + warp_m * 64 + tm * 16 + r0l + half * 8;
            const float invv = gam[m] / sqrtf(var[m] + 1e-5f);
            const float offv = bet[m] - mean[m] * invv;
            const size_t rowbase = ((size_t)bz * 512 + m) * 512 + col0 + warp_n * 32;
#pragma unroll
            for (int tn = 0; tn < 4; tn++) {
                const float bn0 = acc[tm][tn][half * 2 + 0] * invv + offv;
                const float bn1 = acc[tm][tn][half * 2 + 1] * invv + offv;
                const bool s0 = (bn0 >= 2.0f);
                const bool s1 = (bn1 >= 2.0f);
                const int ncol = col0 + warp_n * 32 + tn * 8 + c0l;
                if (fabsf(bn0 - 2.0f) < 3e-3f) {
                    int ix = atomicAdd(&g_cnt[stage], 1);
                    if (ix < FIXCAP)
                        g_fix[stage][ix] = (uint32_t)which | ((uint32_t)bz << 2) |
                                           ((uint32_t)m << 5) | ((uint32_t)ncol << 14);
                }
                if (fabsf(bn1 - 2.0f) < 3e-3f) {
                    int ix = atomicAdd(&g_cnt[stage], 1);
                    if (ix < FIXCAP)
                        g_fix[stage][ix] = (uint32_t)which | ((uint32_t)bz << 2) |
                                           ((uint32_t)m << 5) | ((uint32_t)(ncol + 1) << 14);
                }
                const size_t o = rowbase + tn * 8 + c0l;
                if (OUT_U8) {
                    *(unsigned short*)((uint8_t*)Out + o) =
                        (unsigned short)((s0 ? 1u : 0u) | ((s1 ? 1u : 0u) << 8));
                } else {
                    *(float2*)((float*)Out + o) = make_float2(s0 ? 1.f : 0.f, s1 ? 1.f : 0.f);
                }
            }
        }
    }
}

struct QKVp {
    const bf16 *A0[3], *A1[3], *B0[3], *B1[3];
    uint8_t* out[3];
    const float *gam[3], *bet[3], *mean[3], *var[3];
};

__global__ __launch_bounds__(256, 1) void gemm_qkv(QKVp P) {
    extern __shared__ char sm[];
    const int which = blockIdx.z >> 3;
    const int bz = blockIdx.z & 7;
    gemm_body<2, true>(P.A0[which], P.A1[which], P.B0[which], P.B1[which], P.out[which],
                       P.gam[which], P.bet[which], P.mean[which], P.var[which],
                       bz, 0, which, sm);
}

__global__ __launch_bounds__(256, 1) void gemm_proj(const bf16* A0, const bf16* A1,
                                                    const bf16* B0, float* Out,
                                                    const float* g, const float* b,
                                                    const float* m, const float* v) {
    extern __shared__ char sm[];
    gemm_body<1, false>(A0, A1, B0, B0, Out, g, b, m, v, blockIdx.z, 1, 0, sm);
}

// ---------------- exact fp64 fixup of borderline spikes (coalesced) ----------------
struct FixQ {
    const float* inT[3];   // fp32 transposed [b][n][c]
    const float* w[3];
    const float *g[3], *be[3], *mn[3], *vr[3];
    uint8_t* out[3];
};

__global__ __launch_bounds__(256) void fixup_qkv(FixQ P) {
    const int cnt0 = g_cnt[0];
    const int cnt = cnt0 < FIXCAP ? cnt0 : FIXCAP;
    const int lane = threadIdx.x & 31;
    const int warp = (blockIdx.x * blockDim.x + threadIdx.x) >> 5;
    const int nwarps = (gridDim.x * blockDim.x) >> 5;
    for (int e = warp; e < cnt; e += nwarps) {
        const uint32_t t = g_fix[0][e];
        const int which = t & 3, b = (t >> 2) & 7, m = (t >> 5) & 511, n = (t >> 14) & 511;
        const float* W = P.w[which] + (size_t)m * 512;
        const float* X = P.inT[which] + ((size_t)b * 512 + n) * 512;   // contiguous row
        double s = 0.0;
#pragma unroll
        for (int c0 = 0; c0 < 512; c0 += 128) {
            const int c = c0 + lane * 4;
            const float4 wv = *(const float4*)(W + c);
            const float4 xv = *(const float4*)(X + c);
            s += (double)wv.x * (double)xv.x + (double)wv.y * (double)xv.y +
                 (double)wv.z * (double)xv.z + (double)wv.w * (double)xv.w;
        }
#pragma unroll
        for (int o = 16; o; o >>= 1) s += __shfl_down_sync(0xffffffffu, s, o);
        if (lane == 0) {
            const double inv = (double)P.g[which][m] / sqrt((double)P.vr[which][m] + 1e-5);
            const double bn = s * inv + ((double)P.be[which][m] - (double)P.mn[which][m] * inv);
            P.out[which][((size_t)b * 512 + m) * 512 + n] = (bn >= 2.0) ? (uint8_t)1 : (uint8_t)0;
        }
    }
}

__global__ __launch_bounds__(256) void fixup_proj(const float* __restrict__ pw,
                                                  const bf16* __restrict__ sT, float* __restrict__ out,
                                                  const float* __restrict__ g, const float* __restrict__ be,
                                                  const float* __restrict__ mn, const float* __restrict__ vr) {
    const int cnt0 = g_cnt[1];
    const int cnt = cnt0 < FIXCAP ? cnt0 : FIXCAP;
    const int lane = threadIdx.x & 31;
    const int warp = (blockIdx.x * blockDim.x + threadIdx.x) >> 5;
    const int nwarps = (gridDim.x * blockDim.x) >> 5;
    for (int e = warp; e < cnt; e += nwarps) {
        const uint32_t t = g_fix[1][e];
        const int b = (t >> 2) & 7, m = (t >> 5) & 511, n = (t >> 14) & 511;
        const float* W = pw + (size_t)m * 512;
        const bf16* S = sT + ((size_t)b * 512 + n) * 512;   // contiguous row
        double s = 0.0;
#pragma unroll
        for (int c0 = 0; c0 < 512; c0 += 256) {
            const int c = c0 + lane * 8;
            // 8 bf16 = 16B per lane
            const uint4 sv = *(const uint4*)(S + c);
            const float4 w0 = *(const float4*)(W + c);
            const float4 w1 = *(const float4*)(W + c + 4);
            const __nv_bfloat162* sp = (const __nv_bfloat162*)&sv;
            float2 f0 = __bfloat1622float2(sp[0]);
            float2 f1 = __bfloat1622float2(sp[1]);
            float2 f2 = __bfloat1622float2(sp[2]);
            float2 f3 = __bfloat1622float2(sp[3]);
            s += (double)w0.x * f0.x + (double)w0.y * f0.y +
                 (double)w0.z * f1.x + (double)w0.w * f1.y +
                 (double)w1.x * f2.x + (double)w1.y * f2.y +
                 (double)w1.z * f3.x + (double)w1.w * f3.y;
        }
#pragma unroll
        for (int o = 16; o; o >>= 1) s += __shfl_down_sync(0xffffffffu, s, o);
        if (lane == 0) {
            const double inv = (double)g[m] / sqrt((double)vr[m] + 1e-5);
            const double bn = s * inv + ((double)be[m] - (double)mn[m] * inv);
            out[((size_t)b * 512 + m) * 512 + n] = (bn >= 2.0) ? 1.0f : 0.0f;
        }
    }
}

// ---------------- spiking attention: o = Q (K^T V), exact int math ----------------
__global__ __launch_bounds__(512)
void attn_lif(const uint8_t* __restrict__ q, const uint8_t* __restrict__ k,
              const uint8_t* __restrict__ v, bf16* __restrict__ sT) {
    __shared__ uint32_t ks[32 * 133];
    __shared__ uint32_t vs[32 * 133];
    __shared__ int M[32][33];

    const int tid = threadIdx.x;
    const int tb = blockIdx.x >> 4;
    const int h = blockIdx.x & 15;
    const size_t base = ((size_t)tb * 512 + h * 32) * 512;

    const uint32_t* ksrc = (const uint32_t*)(k + base);
    const uint32_t* vsrc = (const uint32_t*)(v + base);
    for (int f = tid; f < 2 * 4096; f += 512) {
        const int r = (f >> 7) & 31, w = f & 127;
        if (f < 4096) ks[r * 133 + w] = ksrc[r * 128 + w];
        else          vs[r * 133 + w] = vsrc[r * 128 + w];
    }
    __syncthreads();

    if (tid < 256) {
        const int dp = tid >> 3, dd0 = (tid & 7) * 4;
        unsigned a0 = 0, a1 = 0, a2 = 0, a3 = 0;
        const uint32_t* kr = &ks[dp * 133];
        const uint32_t* v0 = &vs[(dd0 + 0) * 133];
        const uint32_t* v1 = &vs[(dd0 + 1) * 133];
        const uint32_t* v2 = &vs[(dd0 + 2) * 133];
        const uint32_t* v3 = &vs[(dd0 + 3) * 133];
#pragma unroll 8
        for (int w = 0; w < 128; w++) {
            const uint32_t kw = kr[w];
            a0 = __dp4a(kw, v0[w], a0);
            a1 = __dp4a(kw, v1[w], a1);
            a2 = __dp4a(kw, v2[w], a2);
            a3 = __dp4a(kw, v3[w], a3);
        }
        M[dp][dd0 + 0] = (int)a0; M[dp][dd0 + 1] = (int)a1;
        M[dp][dd0 + 2] = (int)a2; M[dp][dd0 + 3] = (int)a3;
    }
    __syncthreads();

    const int n = tid;
    int oacc[32];
#pragma unroll
    for (int d = 0; d < 32; d++) oacc[d] = 0;
#pragma unroll 4
    for (int dp = 0; dp < 32; dp++) {
        if (q[base + (size_t)dp * 512 + n]) {
#pragma unroll
            for (int d = 0; d < 32; d++) oacc[d] += M[dp][d];
        }
    }
    // LIF(o*0.25/2) == (o_int >= 8). Write spikes^T as bf16 {0,1} at [b][n][c].
    uint32_t* dst = (uint32_t*)(sT + ((size_t)tb * 512 + n) * 512 + h * 32);
#pragma unroll
    for (int g = 0; g < 16; g++) {
        const uint32_t lo = (oacc[2 * g] >= 8) ? 0x3F80u : 0u;
        const uint32_t hi = (oacc[2 * g + 1] >= 8) ? 0x3F80u : 0u;
        dst[g] = lo | (hi << 16);
    }
}

// ---------------------------------------------------------------------------
extern "C" void kernel_launch(void* const* d_in, const int* in_sizes, int n_in,
                              void* d_out, int out_size) {
    (void)in_sizes; (void)n_in; (void)out_size;
    const float* x = (const float*)d_in[0];
    const float* y = (const float*)d_in[1];
    const float* w[4]  = {(const float*)d_in[2], (const float*)d_in[7], (const float*)d_in[12], (const float*)d_in[17]};
    const float* bg[4] = {(const float*)d_in[3], (const float*)d_in[8], (const float*)d_in[13], (const float*)d_in[18]};
    const float* bb[4] = {(const float*)d_in[4], (const float*)d_in[9], (const float*)d_in[14], (const float*)d_in[19]};
    const float* bm[4] = {(const float*)d_in[5], (const float*)d_in[10], (const float*)d_in[15], (const float*)d_in[20]};
    const float* bv[4] = {(const float*)d_in[6], (const float*)d_in[11], (const float*)d_in[16], (const float*)d_in[21]};

    bf16 *wsp, *xT, *yT, *sT;
    float *xTf, *yTf;
    uint8_t *gq, *gk, *gv;
    cudaGetSymbolAddress((void**)&wsp, g_wsp);
    cudaGetSymbolAddress((void**)&xT, g_xT);
    cudaGetSymbolAddress((void**)&yT, g_yT);
    cudaGetSymbolAddress((void**)&xTf, g_xTf);
    cudaGetSymbolAddress((void**)&yTf, g_yTf);
    cudaGetSymbolAddress((void**)&sT, g_sT);
    cudaGetSymbolAddress((void**)&gq, g_q);
    cudaGetSymbolAddress((void**)&gk, g_k);
    cudaGetSymbolAddress((void**)&gv, g_v);

    cudaFuncSetAttribute(gemm_qkv, cudaFuncAttributeMaxDynamicSharedMemorySize, 131072);
    cudaFuncSetAttribute(gemm_proj, cudaFuncAttributeMaxDynamicSharedMemorySize, 98304);

    prep_split4<<<dim3(64, 4), 256>>>(w[0], w[1], w[2], w[3], wsp);
    prep_xyT<<<dim3(16, 16, 16), 256>>>(x, y, xT, yT, xTf, yTf);

    QKVp P;
    uint8_t* outs[3] = {gq, gk, gv};
    for (int g = 0; g < 3; g++) {
        P.A0[g] = wsp + (size_t)(g * 2 + 0) * WSZ;
        P.A1[g] = wsp + (size_t)(g * 2 + 1) * WSZ;
        P.B0[g] = (g == 0) ? xT : yT;
        P.B1[g] = ((g == 0) ? xT : yT) + (size_t)XSZ;
        P.out[g] = outs[g];
        P.gam[g] = bg[g]; P.bet[g] = bb[g]; P.mean[g] = bm[g]; P.var[g] = bv[g];
    }
    gemm_qkv<<<dim3(4, 4, 24), 256, 131072>>>(P);

    FixQ F;
    F.inT[0] = xTf; F.inT[1] = yTf; F.inT[2] = yTf;
    for (int g = 0; g < 3; g++) {
        F.w[g] = w[g]; F.g[g] = bg[g]; F.be[g] = bb[g]; F.mn[g] = bm[g]; F.vr[g] = bv[g];
        F.out[g] = outs[g];
    }
    fixup_qkv<<<128, 256>>>(F);

    attn_lif<<<128, 512>>>(gq, gk, gv, sT);

    gemm_proj<<<dim3(4, 4, 8), 256, 98304>>>(wsp + 6 * (size_t)WSZ, wsp + 7 * (size_t)WSZ,
                                             sT, (float*)d_out, bg[3], bb[3], bm[3], bv[3]);

    fixup_proj<<<128, 256>>>(w[3], sT, (float*)d_out, bg[3], bb[3], bm[3], bv[3]);
}

// round 9
// speedup vs baseline: 1.0290x; 1.0290x over previous
#include <cuda_runtime.h>
#include <cuda_bf16.h>
#include <cstdint>

typedef __nv_bfloat16 bf16;

#define WSZ (512*512)
#define XSZ (8*512*512)
#define FIXCAP (1<<20)

// ---------------- device scratch ----------------
__device__ bf16     g_wsp[4][2][WSZ];   // weight splits (2 levels)
__device__ bf16     g_xT[2][XSZ];       // x^T splits [b][n][c]
__device__ bf16     g_yT[2][XSZ];       // y^T splits
__device__ uint8_t  g_q[XSZ], g_k[XSZ], g_v[XSZ];
__device__ bf16     g_sT[XSZ];          // attn spikes^T bf16 [b][n][c]
__device__ int      g_cnt[2];
__device__ uint32_t g_fix[2][FIXCAP];

// ---------------- PTX helpers (arch-generic, sm_80+) ----------------
__device__ __forceinline__ uint32_t smem_u32(const void* p) {
    uint32_t a;
    asm("{ .reg .u64 t; cvta.to.shared.u64 t, %1; cvt.u32.u64 %0, t; }" : "=r"(a) : "l"(p));
    return a;
}
__device__ __forceinline__ void cp16(uint32_t dst, const void* src) {
    asm volatile("cp.async.cg.shared.global [%0], [%1], 16;" :: "r"(dst), "l"(src) : "memory");
}
__device__ __forceinline__ void cp_commit() { asm volatile("cp.async.commit_group;" ::: "memory"); }
template<int N> __device__ __forceinline__ void cp_wait() {
    asm volatile("cp.async.wait_group %0;" :: "n"(N) : "memory");
}
__device__ __forceinline__ void ldmx4(uint32_t& r0, uint32_t& r1, uint32_t& r2, uint32_t& r3, uint32_t a) {
    asm volatile("ldmatrix.sync.aligned.m8n8.x4.shared.b16 {%0,%1,%2,%3}, [%4];"
                 : "=r"(r0), "=r"(r1), "=r"(r2), "=r"(r3) : "r"(a));
}
__device__ __forceinline__ void mma_bf16(float& c0, float& c1, float& c2, float& c3,
                                         uint32_t a0, uint32_t a1, uint32_t a2, uint32_t a3,
                                         uint32_t b0, uint32_t b1) {
    asm volatile("mma.sync.aligned.m16n8k16.row.col.f32.bf16.bf16.f32 "
                 "{%0,%1,%2,%3}, {%4,%5,%6,%7}, {%8,%9}, {%0,%1,%2,%3};"
                 : "+f"(c0), "+f"(c1), "+f"(c2), "+f"(c3)
                 : "r"(a0), "r"(a1), "r"(a2), "r"(a3), "r"(b0), "r"(b1));
}

// 2-way bf16 split (truncation): w ≈ h + l, residual ~2^-16 relative
__device__ __forceinline__ void split2(float w, bf16& h, bf16& l) {
    h = __float2bfloat16_rz(w);
    l = __float2bfloat16_rz(w - __bfloat162float(h));
}

// ---------------- prep kernels ----------------
__global__ void prep_split4(const float* __restrict__ w0, const float* __restrict__ w1,
                            const float* __restrict__ w2, const float* __restrict__ w3,
                            bf16* __restrict__ dst) {
    if (blockIdx.x == 0 && blockIdx.y == 0 && threadIdx.x == 0) { g_cnt[0] = 0; g_cnt[1] = 0; }
    const float* ws[4] = {w0, w1, w2, w3};
    const int wi = blockIdx.y;
    const float* w = ws[wi];
    bf16* h = dst + (size_t)(wi * 2 + 0) * WSZ;
    bf16* l = dst + (size_t)(wi * 2 + 1) * WSZ;
    for (int i = blockIdx.x * 256 + threadIdx.x; i < WSZ; i += gridDim.x * 256) {
        bf16 a, b;
        split2(w[i], a, b);
        h[i] = a; l[i] = b;
    }
}

// transpose [b][c][n] -> [b][n][c] with 2-way split; z<8: x->xT, z>=8: y->yT
__global__ void prep_xyT(const float* __restrict__ x, const float* __restrict__ y,
                         bf16* __restrict__ xT, bf16* __restrict__ yT) {
    __shared__ float t[32][33];
    const int z = blockIdx.z;
    const int b = z & 7;
    const float* src0 = (z < 8) ? x : y;
    bf16* d0 = (z < 8) ? xT : yT;
    const int c0 = blockIdx.y * 32, n0 = blockIdx.x * 32;
    const int r = threadIdx.x >> 5, j = threadIdx.x & 31;
    const float* src = src0 + ((size_t)b * 512 + c0) * 512 + n0;
#pragma unroll
    for (int i = r; i < 32; i += 8) t[i][j] = src[(size_t)i * 512 + j];
    __syncthreads();
    const size_t dst = ((size_t)b * 512 + n0) * 512 + c0;
#pragma unroll
    for (int i = r; i < 32; i += 8) {
        bf16 a, bb;
        split2(t[j][i], a, bb);
        d0[0 * (size_t)XSZ + dst + (size_t)i * 512 + j] = a;
        d0[1 * (size_t)XSZ + dst + (size_t)i * 512 + j] = bb;
    }
}

// ---------------- bf16 mma GEMM + BN + LIF (+ borderline flagging) ----------------
// D = A0*B0 + A0*B1 + A1*B0 (NB=2)  or  A0*B0 + A1*B0 (NB=1)
// 128x128 tile, BK=64, 8 stages, double-buffered cp.async, 256 threads (2x4 warps).
template<int NB, bool OUT_U8>
__device__ __forceinline__ void gemm_body(const bf16* __restrict__ A0, const bf16* __restrict__ A1,
                                          const bf16* __restrict__ B0, const bf16* __restrict__ B1,
                                          void* Out,
                                          const float* __restrict__ gam, const float* __restrict__ bet,
                                          const float* __restrict__ mean, const float* __restrict__ var,
                                          int bz, int stage, int which, char* sm) {
    const int NT = 2 + NB;                 // tiles per stage
    const int tid = threadIdx.x;
    const int lane = tid & 31, wid = tid >> 5;
    const int warp_m = wid & 1, warp_n = wid >> 1;
    const int row0 = blockIdx.y * 128, col0 = blockIdx.x * 128;
    const uint32_t sbase = smem_u32(sm);

    float acc[4][4][4];
#pragma unroll
    for (int i = 0; i < 4; i++)
#pragma unroll
        for (int j = 0; j < 4; j++)
#pragma unroll
            for (int q = 0; q < 4; q++) acc[i][j][q] = 0.0f;

    const bf16* srcs[4];
    srcs[0] = A0 + (size_t)row0 * 512;
    srcs[1] = A1 + (size_t)row0 * 512;
    srcs[2] = B0 + ((size_t)bz * 512 + col0) * 512;
    if (NB == 2) srcs[3] = B1 + ((size_t)bz * 512 + col0) * 512;

    // stage = NT tiles of [128][64] bf16; tile chunk (r, c): 16B at row r, chunk c^(r&7)
    auto issue = [&](int kt, int stg) {
        const uint32_t sb = sbase + stg * NT * 16384;
#pragma unroll
        for (int t = 0; t < NT; t++) {
            const bf16* base = srcs[t] + (kt << 6);
#pragma unroll
            for (int i = 0; i < 4; i++) {
                const int idx = tid + i * 256;
                const int r = idx >> 3, c = idx & 7;
                const uint32_t off = r * 128 + ((c ^ (r & 7)) << 4);
                cp16(sb + t * 16384 + off, base + (size_t)r * 512 + c * 8);
            }
        }
        cp_commit();
    };

    auto ldA = [&](uint32_t Af[4][4], uint32_t sA, int ks) {
#pragma unroll
        for (int tm = 0; tm < 4; tm++) {
            const int r = warp_m * 64 + tm * 16 + (lane & 15);
            const int ch = ks * 2 + (lane >> 4);
            ldmx4(Af[tm][0], Af[tm][1], Af[tm][2], Af[tm][3],
                  sA + r * 128 + ((ch ^ (r & 7)) << 4));
        }
    };
    auto ldB = [&](uint32_t Bf[2][4], uint32_t sB, int ks) {
#pragma unroll
        for (int tp = 0; tp < 2; tp++) {
            const int r = warp_n * 32 + tp * 16 + (lane & 7) + ((lane & 16) >> 1);
            const int ch = ks * 2 + ((lane >> 3) & 1);
            ldmx4(Bf[tp][0], Bf[tp][1], Bf[tp][2], Bf[tp][3],
                  sB + r * 128 + ((ch ^ (r & 7)) << 4));
        }
    };
    auto pass = [&](uint32_t Af[4][4], uint32_t Bf[2][4]) {
#pragma unroll
        for (int tm = 0; tm < 4; tm++)
#pragma unroll
            for (int tn = 0; tn < 4; tn++)
                mma_bf16(acc[tm][tn][0], acc[tm][tn][1], acc[tm][tn][2], acc[tm][tn][3],
                         Af[tm][0], Af[tm][1], Af[tm][2], Af[tm][3],
                         Bf[tn >> 1][(tn & 1) * 2], Bf[tn >> 1][(tn & 1) * 2 + 1]);
    };

    auto compute = [&](int stg) {
        const uint32_t sb = sbase + stg * NT * 16384;
#pragma unroll
        for (int ks = 0; ks < 4; ks++) {
            uint32_t Af0[4][4], Af1[4][4], Bf0[2][4];
            ldA(Af0, sb, ks);
            ldB(Bf0, sb + 2 * 16384, ks);
            ldA(Af1, sb + 16384, ks);
            if (NB == 2) {
                uint32_t Bf1[2][4];
                ldB(Bf1, sb + 3 * 16384, ks);
                pass(Af0, Bf0);
                pass(Af0, Bf1);
                pass(Af1, Bf0);
            } else {
                pass(Af0, Bf0);
                pass(Af1, Bf0);
            }
        }
    };

    issue(0, 0);
    for (int kt = 0; kt < 8; kt++) {
        if (kt + 1 < 8) { issue(kt + 1, (kt + 1) & 1); cp_wait<1>(); }
        else cp_wait<0>();
        __syncthreads();
        compute(kt & 1);
        __syncthreads();
    }

    // ---- epilogue: BN + LIF; flag borderline values for exact fp64 fixup ----
    const int r0l = lane >> 2, c0l = (lane & 3) * 2;
#pragma unroll
    for (int tm = 0; tm < 4; tm++) {
#pragma unroll
        for (int half = 0; half < 2; half++) {
            const int m = row0 + warp_m * 64 + tm * 16 + r0l + half * 8;
            const float invv = gam[m] / sqrtf(var[m] + 1e-5f);
            const float offv = bet[m] - mean[m] * invv;
            const size_t rowbase = ((size_t)bz * 512 + m) * 512 + col0 + warp_n * 32;
#pragma unroll
            for (int tn = 0; tn < 4; tn++) {
                const float bn0 = acc[tm][tn][half * 2 + 0] * invv + offv;
                const float bn1 = acc[tm][tn][half * 2 + 1] * invv + offv;
                const bool s0 = (bn0 >= 2.0f);
                const bool s1 = (bn1 >= 2.0f);
                const int ncol = col0 + warp_n * 32 + tn * 8 + c0l;
                if (fabsf(bn0 - 2.0f) < 3e-3f) {
                    int ix = atomicAdd(&g_cnt[stage], 1);
                    if (ix < FIXCAP)
                        g_fix[stage][ix] = (uint32_t)which | ((uint32_t)bz << 2) |
                                           ((uint32_t)m << 5) | ((uint32_t)ncol << 14);
                }
                if (fabsf(bn1 - 2.0f) < 3e-3f) {
                    int ix = atomicAdd(&g_cnt[stage], 1);
                    if (ix < FIXCAP)
                        g_fix[stage][ix] = (uint32_t)which | ((uint32_t)bz << 2) |
                                           ((uint32_t)m << 5) | ((uint32_t)(ncol + 1) << 14);
                }
                const size_t o = rowbase + tn * 8 + c0l;
                if (OUT_U8) {
                    *(unsigned short*)((uint8_t*)Out + o) =
                        (unsigned short)((s0 ? 1u : 0u) | ((s1 ? 1u : 0u) << 8));
                } else {
                    *(float2*)((float*)Out + o) = make_float2(s0 ? 1.f : 0.f, s1 ? 1.f : 0.f);
                }
            }
        }
    }
}

struct QKVp {
    const bf16 *A0[3], *A1[3], *B0[3], *B1[3];
    uint8_t* out[3];
    const float *gam[3], *bet[3], *mean[3], *var[3];
};

__global__ __launch_bounds__(256, 1) void gemm_qkv(QKVp P) {
    extern __shared__ char sm[];
    const int which = blockIdx.z >> 3;
    const int bz = blockIdx.z & 7;
    gemm_body<2, true>(P.A0[which], P.A1[which], P.B0[which], P.B1[which], P.out[which],
                       P.gam[which], P.bet[which], P.mean[which], P.var[which],
                       bz, 0, which, sm);
}

__global__ __launch_bounds__(256, 1) void gemm_proj(const bf16* A0, const bf16* A1,
                                                    const bf16* B0, float* Out,
                                                    const float* g, const float* b,
                                                    const float* m, const float* v) {
    extern __shared__ char sm[];
    gemm_body<1, false>(A0, A1, B0, B0, Out, g, b, m, v, blockIdx.z, 1, 0, sm);
}

// ---------------- exact fp64 fixup of borderline spikes ----------------
// One warp per flagged element; 16 independent loads hoisted (MLP), 4 fp64 accumulators.
struct FixQ {
    const float* in[3];    // original [b][c][n]
    const float* w[3];
    const float *g[3], *be[3], *mn[3], *vr[3];
    uint8_t* out[3];
};

__global__ __launch_bounds__(256) void fixup_qkv(FixQ P) {
    const int cnt0 = g_cnt[0];
    const int cnt = cnt0 < FIXCAP ? cnt0 : FIXCAP;
    const int lane = threadIdx.x & 31;
    const int warp = (blockIdx.x * blockDim.x + threadIdx.x) >> 5;
    const int nwarps = (gridDim.x * blockDim.x) >> 5;
    for (int e = warp; e < cnt; e += nwarps) {
        const uint32_t t = g_fix[0][e];
        const int which = t & 3, b = (t >> 2) & 7, m = (t >> 5) & 511, n = (t >> 14) & 511;
        const float* W = P.w[which] + (size_t)m * 512 + lane;
        const float* X = P.in[which] + (size_t)b * 262144 + n + (size_t)lane * 512;
        float wr[16], xr[16];
#pragma unroll
        for (int i = 0; i < 16; i++) {        // independent loads, MLP=32
            wr[i] = W[i * 32];
            xr[i] = X[(size_t)i * 32 * 512];
        }
        double s0 = 0.0, s1 = 0.0, s2 = 0.0, s3 = 0.0;
#pragma unroll
        for (int i = 0; i < 16; i += 4) {     // 4 independent fp64 chains
            s0 += (double)wr[i + 0] * (double)xr[i + 0];
            s1 += (double)wr[i + 1] * (double)xr[i + 1];
            s2 += (double)wr[i + 2] * (double)xr[i + 2];
            s3 += (double)wr[i + 3] * (double)xr[i + 3];
        }
        double s = (s0 + s1) + (s2 + s3);
#pragma unroll
        for (int o = 16; o; o >>= 1) s += __shfl_down_sync(0xffffffffu, s, o);
        if (lane == 0) {
            const double inv = (double)P.g[which][m] / sqrt((double)P.vr[which][m] + 1e-5);
            const double bn = s * inv + ((double)P.be[which][m] - (double)P.mn[which][m] * inv);
            P.out[which][((size_t)b * 512 + m) * 512 + n] = (bn >= 2.0) ? (uint8_t)1 : (uint8_t)0;
        }
    }
}

__global__ __launch_bounds__(256) void fixup_proj(const float* __restrict__ pw,
                                                  const bf16* __restrict__ sT, float* __restrict__ out,
                                                  const float* __restrict__ g, const float* __restrict__ be,
                                                  const float* __restrict__ mn, const float* __restrict__ vr) {
    const int cnt0 = g_cnt[1];
    const int cnt = cnt0 < FIXCAP ? cnt0 : FIXCAP;
    const int lane = threadIdx.x & 31;
    const int warp = (blockIdx.x * blockDim.x + threadIdx.x) >> 5;
    const int nwarps = (gridDim.x * blockDim.x) >> 5;
    for (int e = warp; e < cnt; e += nwarps) {
        const uint32_t t = g_fix[1][e];
        const int b = (t >> 2) & 7, m = (t >> 5) & 511, n = (t >> 14) & 511;
        const float* W = pw + (size_t)m * 512 + lane;
        const bf16* S = sT + ((size_t)b * 512 + n) * 512 + lane;
        float wr[16], xr[16];
#pragma unroll
        for (int i = 0; i < 16; i++) {
            wr[i] = W[i * 32];
            xr[i] = __bfloat162float(S[i * 32]);
        }
        double s0 = 0.0, s1 = 0.0, s2 = 0.0, s3 = 0.0;
#pragma unroll
        for (int i = 0; i < 16; i += 4) {
            s0 += (double)wr[i + 0] * (double)xr[i + 0];
            s1 += (double)wr[i + 1] * (double)xr[i + 1];
            s2 += (double)wr[i + 2] * (double)xr[i + 2];
            s3 += (double)wr[i + 3] * (double)xr[i + 3];
        }
        double s = (s0 + s1) + (s2 + s3);
#pragma unroll
        for (int o = 16; o; o >>= 1) s += __shfl_down_sync(0xffffffffu, s, o);
        if (lane == 0) {
            const double inv = (double)g[m] / sqrt((double)vr[m] + 1e-5);
            const double bn = s * inv + ((double)be[m] - (double)mn[m] * inv);
            out[((size_t)b * 512 + m) * 512 + n] = (bn >= 2.0) ? 1.0f : 0.0f;
        }
    }
}

// ---------------- spiking attention: o = Q (K^T V), exact int math ----------------
__global__ __launch_bounds__(512)
void attn_lif(const uint8_t* __restrict__ q, const uint8_t* __restrict__ k,
              const uint8_t* __restrict__ v, bf16* __restrict__ sT) {
    __shared__ uint32_t ks[32 * 133];
    __shared__ uint32_t vs[32 * 133];
    __shared__ int M[32][33];

    const int tid = threadIdx.x;
    const int tb = blockIdx.x >> 4;
    const int h = blockIdx.x & 15;
    const size_t base = ((size_t)tb * 512 + h * 32) * 512;

    const uint32_t* ksrc = (const uint32_t*)(k + base);
    const uint32_t* vsrc = (const uint32_t*)(v + base);
    for (int f = tid; f < 2 * 4096; f += 512) {
        const int r = (f >> 7) & 31, w = f & 127;
        if (f < 4096) ks[r * 133 + w] = ksrc[r * 128 + w];
        else          vs[r * 133 + w] = vsrc[r * 128 + w];
    }
    __syncthreads();

    if (tid < 256) {
        const int dp = tid >> 3, dd0 = (tid & 7) * 4;
        unsigned a0 = 0, a1 = 0, a2 = 0, a3 = 0;
        const uint32_t* kr = &ks[dp * 133];
        const uint32_t* v0 = &vs[(dd0 + 0) * 133];
        const uint32_t* v1 = &vs[(dd0 + 1) * 133];
        const uint32_t* v2 = &vs[(dd0 + 2) * 133];
        const uint32_t* v3 = &vs[(dd0 + 3) * 133];
#pragma unroll 8
        for (int w = 0; w < 128; w++) {
            const uint32_t kw = kr[w];
            a0 = __dp4a(kw, v0[w], a0);
            a1 = __dp4a(kw, v1[w], a1);
            a2 = __dp4a(kw, v2[w], a2);
            a3 = __dp4a(kw, v3[w], a3);
        }
        M[dp][dd0 + 0] = (int)a0; M[dp][dd0 + 1] = (int)a1;
        M[dp][dd0 + 2] = (int)a2; M[dp][dd0 + 3] = (int)a3;
    }
    __syncthreads();

    const int n = tid;
    int oacc[32];
#pragma unroll
    for (int d = 0; d < 32; d++) oacc[d] = 0;
#pragma unroll 4
    for (int dp = 0; dp < 32; dp++) {
        if (q[base + (size_t)dp * 512 + n]) {
#pragma unroll
            for (int d = 0; d < 32; d++) oacc[d] += M[dp][d];
        }
    }
    // LIF(o*0.25/2) == (o_int >= 8). Write spikes^T as bf16 {0,1} at [b][n][c].
    uint32_t* dst = (uint32_t*)(sT + ((size_t)tb * 512 + n) * 512 + h * 32);
#pragma unroll
    for (int g = 0; g < 16; g++) {
        const uint32_t lo = (oacc[2 * g] >= 8) ? 0x3F80u : 0u;
        const uint32_t hi = (oacc[2 * g + 1] >= 8) ? 0x3F80u : 0u;
        dst[g] = lo | (hi << 16);
    }
}

// ---------------------------------------------------------------------------
extern "C" void kernel_launch(void* const* d_in, const int* in_sizes, int n_in,
                              void* d_out, int out_size) {
    (void)in_sizes; (void)n_in; (void)out_size;
    const float* x = (const float*)d_in[0];
    const float* y = (const float*)d_in[1];
    const float* w[4]  = {(const float*)d_in[2], (const float*)d_in[7], (const float*)d_in[12], (const float*)d_in[17]};
    const float* bg[4] = {(const float*)d_in[3], (const float*)d_in[8], (const float*)d_in[13], (const float*)d_in[18]};
    const float* bb[4] = {(const float*)d_in[4], (const float*)d_in[9], (const float*)d_in[14], (const float*)d_in[19]};
    const float* bm[4] = {(const float*)d_in[5], (const float*)d_in[10], (const float*)d_in[15], (const float*)d_in[20]};
    const float* bv[4] = {(const float*)d_in[6], (const float*)d_in[11], (const float*)d_in[16], (const float*)d_in[21]};

    bf16 *wsp, *xT, *yT, *sT;
    uint8_t *gq, *gk, *gv;
    cudaGetSymbolAddress((void**)&wsp, g_wsp);
    cudaGetSymbolAddress((void**)&xT, g_xT);
    cudaGetSymbolAddress((void**)&yT, g_yT);
    cudaGetSymbolAddress((void**)&sT, g_sT);
    cudaGetSymbolAddress((void**)&gq, g_q);
    cudaGetSymbolAddress((void**)&gk, g_k);
    cudaGetSymbolAddress((void**)&gv, g_v);

    cudaFuncSetAttribute(gemm_qkv, cudaFuncAttributeMaxDynamicSharedMemorySize, 131072);
    cudaFuncSetAttribute(gemm_proj, cudaFuncAttributeMaxDynamicSharedMemorySize, 98304);

    prep_split4<<<dim3(64, 4), 256>>>(w[0], w[1], w[2], w[3], wsp);
    prep_xyT<<<dim3(16, 16, 16), 256>>>(x, y, xT, yT);

    QKVp P;
    uint8_t* outs[3] = {gq, gk, gv};
    for (int g = 0; g < 3; g++) {
        P.A0[g] = wsp + (size_t)(g * 2 + 0) * WSZ;
        P.A1[g] = wsp + (size_t)(g * 2 + 1) * WSZ;
        P.B0[g] = (g == 0) ? xT : yT;
        P.B1[g] = ((g == 0) ? xT : yT) + (size_t)XSZ;
        P.out[g] = outs[g];
        P.gam[g] = bg[g]; P.bet[g] = bb[g]; P.mean[g] = bm[g]; P.var[g] = bv[g];
    }
    gemm_qkv<<<dim3(4, 4, 24), 256, 131072>>>(P);

    FixQ F;
    F.in[0] = x; F.in[1] = y; F.in[2] = y;
    for (int g = 0; g < 3; g++) {
        F.w[g] = w[g]; F.g[g] = bg[g]; F.be[g] = bb[g]; F.mn[g] = bm[g]; F.vr[g] = bv[g];
        F.out[g] = outs[g];
    }
    fixup_qkv<<<512, 256>>>(F);

    attn_lif<<<128, 512>>>(gq, gk, gv, sT);

    gemm_proj<<<dim3(4, 4, 8), 256, 98304>>>(wsp + 6 * (size_t)WSZ, wsp + 7 * (size_t)WSZ,
                                             sT, (float*)d_out, bg[3], bb[3], bm[3], bv[3]);

    fixup_proj<<<512, 256>>>(w[3], sT, (float*)d_out, bg[3], bb[3], bm[3], bv[3]);
}

// round 10
// speedup vs baseline: 1.2182x; 1.1839x over previous
#include <cuda_runtime.h>
#include <cuda_bf16.h>
#include <cstdint>

typedef __nv_bfloat16 bf16;

#define WSZ (512*512)
#define XSZ (8*512*512)
#define FIXCAP (1<<20)
#define FLAGWIN 5e-4f   // 50-sigma of split-GEMM noise in bn units; still >>6-sigma safe

// ---------------- device scratch ----------------
__device__ bf16     g_wsp[4][2][WSZ];   // weight splits (2 levels)
__device__ bf16     g_xT[2][XSZ];       // x^T splits [b][n][c]
__device__ bf16     g_yT[2][XSZ];       // y^T splits
__device__ uint8_t  g_q[XSZ], g_k[XSZ], g_v[XSZ];
__device__ bf16     g_sT[XSZ];          // attn spikes^T bf16 [b][n][c]
__device__ int      g_cnt[2];
__device__ uint32_t g_fix[2][FIXCAP];

// ---------------- PTX helpers (arch-generic, sm_80+) ----------------
__device__ __forceinline__ uint32_t smem_u32(const void* p) {
    uint32_t a;
    asm("{ .reg .u64 t; cvta.to.shared.u64 t, %1; cvt.u32.u64 %0, t; }" : "=r"(a) : "l"(p));
    return a;
}
__device__ __forceinline__ void cp16(uint32_t dst, const void* src) {
    asm volatile("cp.async.cg.shared.global [%0], [%1], 16;" :: "r"(dst), "l"(src) : "memory");
}
__device__ __forceinline__ void cp_commit() { asm volatile("cp.async.commit_group;" ::: "memory"); }
template<int N> __device__ __forceinline__ void cp_wait() {
    asm volatile("cp.async.wait_group %0;" :: "n"(N) : "memory");
}
__device__ __forceinline__ void ldmx4(uint32_t& r0, uint32_t& r1, uint32_t& r2, uint32_t& r3, uint32_t a) {
    asm volatile("ldmatrix.sync.aligned.m8n8.x4.shared.b16 {%0,%1,%2,%3}, [%4];"
                 : "=r"(r0), "=r"(r1), "=r"(r2), "=r"(r3) : "r"(a));
}
__device__ __forceinline__ void mma_bf16(float& c0, float& c1, float& c2, float& c3,
                                         uint32_t a0, uint32_t a1, uint32_t a2, uint32_t a3,
                                         uint32_t b0, uint32_t b1) {
    asm volatile("mma.sync.aligned.m16n8k16.row.col.f32.bf16.bf16.f32 "
                 "{%0,%1,%2,%3}, {%4,%5,%6,%7}, {%8,%9}, {%0,%1,%2,%3};"
                 : "+f"(c0), "+f"(c1), "+f"(c2), "+f"(c3)
                 : "r"(a0), "r"(a1), "r"(a2), "r"(a3), "r"(b0), "r"(b1));
}

// 2-way bf16 split (truncation): w ≈ h + l, residual ~2^-16 relative
__device__ __forceinline__ void split2(float w, bf16& h, bf16& l) {
    h = __float2bfloat16_rz(w);
    l = __float2bfloat16_rz(w - __bfloat162float(h));
}

// ---------------- prep kernels ----------------
__global__ void prep_split4(const float* __restrict__ w0, const float* __restrict__ w1,
                            const float* __restrict__ w2, const float* __restrict__ w3,
                            bf16* __restrict__ dst) {
    if (blockIdx.x == 0 && blockIdx.y == 0 && threadIdx.x == 0) { g_cnt[0] = 0; g_cnt[1] = 0; }
    const float* ws[4] = {w0, w1, w2, w3};
    const int wi = blockIdx.y;
    const float* w = ws[wi];
    bf16* h = dst + (size_t)(wi * 2 + 0) * WSZ;
    bf16* l = dst + (size_t)(wi * 2 + 1) * WSZ;
    for (int i = blockIdx.x * 256 + threadIdx.x; i < WSZ; i += gridDim.x * 256) {
        bf16 a, b;
        split2(w[i], a, b);
        h[i] = a; l[i] = b;
    }
}

// transpose [b][c][n] -> [b][n][c] with 2-way split; z<8: x->xT, z>=8: y->yT
__global__ void prep_xyT(const float* __restrict__ x, const float* __restrict__ y,
                         bf16* __restrict__ xT, bf16* __restrict__ yT) {
    __shared__ float t[32][33];
    const int z = blockIdx.z;
    const int b = z & 7;
    const float* src0 = (z < 8) ? x : y;
    bf16* d0 = (z < 8) ? xT : yT;
    const int c0 = blockIdx.y * 32, n0 = blockIdx.x * 32;
    const int r = threadIdx.x >> 5, j = threadIdx.x & 31;
    const float* src = src0 + ((size_t)b * 512 + c0) * 512 + n0;
#pragma unroll
    for (int i = r; i < 32; i += 8) t[i][j] = src[(size_t)i * 512 + j];
    __syncthreads();
    const size_t dst = ((size_t)b * 512 + n0) * 512 + c0;
#pragma unroll
    for (int i = r; i < 32; i += 8) {
        bf16 a, bb;
        split2(t[j][i], a, bb);
        d0[0 * (size_t)XSZ + dst + (size_t)i * 512 + j] = a;
        d0[1 * (size_t)XSZ + dst + (size_t)i * 512 + j] = bb;
    }
}

// ---------------- bf16 mma GEMM + BN + LIF (+ borderline flagging) ----------------
// D = A0*B0 + A0*B1 + A1*B0 (NB=2)  or  A0*B0 + A1*B0 (NB=1)
// 128x128 tile, BK=64, 8 stages, double-buffered cp.async, 256 threads (2x4 warps).
template<int NB, bool OUT_U8>
__device__ __forceinline__ void gemm_body(const bf16* __restrict__ A0, const bf16* __restrict__ A1,
                                          const bf16* __restrict__ B0, const bf16* __restrict__ B1,
                                          void* Out,
                                          const float* __restrict__ gam, const float* __restrict__ bet,
                                          const float* __restrict__ mean, const float* __restrict__ var,
                                          int bz, int stage, int which, char* sm) {
    const int NT = 2 + NB;                 // tiles per stage
    const int tid = threadIdx.x;
    const int lane = tid & 31, wid = tid >> 5;
    const int warp_m = wid & 1, warp_n = wid >> 1;
    const int row0 = blockIdx.y * 128, col0 = blockIdx.x * 128;
    const uint32_t sbase = smem_u32(sm);

    float acc[4][4][4];
#pragma unroll
    for (int i = 0; i < 4; i++)
#pragma unroll
        for (int j = 0; j < 4; j++)
#pragma unroll
            for (int q = 0; q < 4; q++) acc[i][j][q] = 0.0f;

    const bf16* srcs[4];
    srcs[0] = A0 + (size_t)row0 * 512;
    srcs[1] = A1 + (size_t)row0 * 512;
    srcs[2] = B0 + ((size_t)bz * 512 + col0) * 512;
    if (NB == 2) srcs[3] = B1 + ((size_t)bz * 512 + col0) * 512;

    // stage = NT tiles of [128][64] bf16; tile chunk (r, c): 16B at row r, chunk c^(r&7)
    auto issue = [&](int kt, int stg) {
        const uint32_t sb = sbase + stg * NT * 16384;
#pragma unroll
        for (int t = 0; t < NT; t++) {
            const bf16* base = srcs[t] + (kt << 6);
#pragma unroll
            for (int i = 0; i < 4; i++) {
                const int idx = tid + i * 256;
                const int r = idx >> 3, c = idx & 7;
                const uint32_t off = r * 128 + ((c ^ (r & 7)) << 4);
                cp16(sb + t * 16384 + off, base + (size_t)r * 512 + c * 8);
            }
        }
        cp_commit();
    };

    auto ldA = [&](uint32_t Af[4][4], uint32_t sA, int ks) {
#pragma unroll
        for (int tm = 0; tm < 4; tm++) {
            const int r = warp_m * 64 + tm * 16 + (lane & 15);
            const int ch = ks * 2 + (lane >> 4);
            ldmx4(Af[tm][0], Af[tm][1], Af[tm][2], Af[tm][3],
                  sA + r * 128 + ((ch ^ (r & 7)) << 4));
        }
    };
    auto ldB = [&](uint32_t Bf[2][4], uint32_t sB, int ks) {
#pragma unroll
        for (int tp = 0; tp < 2; tp++) {
            const int r = warp_n * 32 + tp * 16 + (lane & 7) + ((lane & 16) >> 1);
            const int ch = ks * 2 + ((lane >> 3) & 1);
            ldmx4(Bf[tp][0], Bf[tp][1], Bf[tp][2], Bf[tp][3],
                  sB + r * 128 + ((ch ^ (r & 7)) << 4));
        }
    };
    auto pass = [&](uint32_t Af[4][4], uint32_t Bf[2][4]) {
#pragma unroll
        for (int tm = 0; tm < 4; tm++)
#pragma unroll
            for (int tn = 0; tn < 4; tn++)
                mma_bf16(acc[tm][tn][0], acc[tm][tn][1], acc[tm][tn][2], acc[tm][tn][3],
                         Af[tm][0], Af[tm][1], Af[tm][2], Af[tm][3],
                         Bf[tn >> 1][(tn & 1) * 2], Bf[tn >> 1][(tn & 1) * 2 + 1]);
    };

    auto compute = [&](int stg) {
        const uint32_t sb = sbase + stg * NT * 16384;
#pragma unroll
        for (int ks = 0; ks < 4; ks++) {
            uint32_t Af0[4][4], Af1[4][4], Bf0[2][4];
            ldA(Af0, sb, ks);
            ldB(Bf0, sb + 2 * 16384, ks);
            ldA(Af1, sb + 16384, ks);
            if (NB == 2) {
                uint32_t Bf1[2][4];
                ldB(Bf1, sb + 3 * 16384, ks);
                pass(Af0, Bf0);
                pass(Af0, Bf1);
                pass(Af1, Bf0);
            } else {
                pass(Af0, Bf0);
                pass(Af1, Bf0);
            }
        }
    };

    issue(0, 0);
    for (int kt = 0; kt < 8; kt++) {
        if (kt + 1 < 8) { issue(kt + 1, (kt + 1) & 1); cp_wait<1>(); }
        else cp_wait<0>();
        __syncthreads();
        compute(kt & 1);
        __syncthreads();
    }

    // ---- epilogue: BN + LIF; flag borderline values for exact fp64 fixup ----
    const int r0l = lane >> 2, c0l = (lane & 3) * 2;
#pragma unroll
    for (int tm = 0; tm < 4; tm++) {
#pragma unroll
        for (int half = 0; half < 2; half++) {
            const int m = row0 + warp_m * 64 + tm * 16 + r0l + half * 8;
            const float invv = gam[m] / sqrtf(var[m] + 1e-5f);
            const float offv = bet[m] - mean[m] * invv;
            const size_t rowbase = ((size_t)bz * 512 + m) * 512 + col0 + warp_n * 32;
#pragma unroll
            for (int tn = 0; tn < 4; tn++) {
                const float bn0 = acc[tm][tn][half * 2 + 0] * invv + offv;
                const float bn1 = acc[tm][tn][half * 2 + 1] * invv + offv;
                const bool s0 = (bn0 >= 2.0f);
                const bool s1 = (bn1 >= 2.0f);
                const int ncol = col0 + warp_n * 32 + tn * 8 + c0l;
                if (fabsf(bn0 - 2.0f) < FLAGWIN) {
                    int ix = atomicAdd(&g_cnt[stage], 1);
                    if (ix < FIXCAP)
                        g_fix[stage][ix] = (uint32_t)which | ((uint32_t)bz << 2) |
                                           ((uint32_t)m << 5) | ((uint32_t)ncol << 14);
                }
                if (fabsf(bn1 - 2.0f) < FLAGWIN) {
                    int ix = atomicAdd(&g_cnt[stage], 1);
                    if (ix < FIXCAP)
                        g_fix[stage][ix] = (uint32_t)which | ((uint32_t)bz << 2) |
                                           ((uint32_t)m << 5) | ((uint32_t)(ncol + 1) << 14);
                }
                const size_t o = rowbase + tn * 8 + c0l;
                if (OUT_U8) {
                    *(unsigned short*)((uint8_t*)Out + o) =
                        (unsigned short)((s0 ? 1u : 0u) | ((s1 ? 1u : 0u) << 8));
                } else {
                    *(float2*)((float*)Out + o) = make_float2(s0 ? 1.f : 0.f, s1 ? 1.f : 0.f);
                }
            }
        }
    }
}

struct QKVp {
    const bf16 *A0[3], *A1[3], *B0[3], *B1[3];
    uint8_t* out[3];
    const float *gam[3], *bet[3], *mean[3], *var[3];
};

__global__ __launch_bounds__(256, 1) void gemm_qkv(QKVp P) {
    extern __shared__ char sm[];
    const int which = blockIdx.z >> 3;
    const int bz = blockIdx.z & 7;
    gemm_body<2, true>(P.A0[which], P.A1[which], P.B0[which], P.B1[which], P.out[which],
                       P.gam[which], P.bet[which], P.mean[which], P.var[which],
                       bz, 0, which, sm);
}

__global__ __launch_bounds__(256, 1) void gemm_proj(const bf16* A0, const bf16* A1,
                                                    const bf16* B0, float* Out,
                                                    const float* g, const float* b,
                                                    const float* m, const float* v) {
    extern __shared__ char sm[];
    gemm_body<1, false>(A0, A1, B0, B0, Out, g, b, m, v, blockIdx.z, 1, 0, sm);
}

// ---------------- exact fp64 fixup of borderline spikes ----------------
struct FixQ {
    const float* in[3];    // original [b][c][n]
    const float* w[3];
    const float *g[3], *be[3], *mn[3], *vr[3];
    uint8_t* out[3];
};

__global__ __launch_bounds__(256) void fixup_qkv(FixQ P) {
    const int cnt0 = g_cnt[0];
    const int cnt = cnt0 < FIXCAP ? cnt0 : FIXCAP;
    const int lane = threadIdx.x & 31;
    const int warp = (blockIdx.x * blockDim.x + threadIdx.x) >> 5;
    const int nwarps = (gridDim.x * blockDim.x) >> 5;
    for (int e = warp; e < cnt; e += nwarps) {
        const uint32_t t = g_fix[0][e];
        const int which = t & 3, b = (t >> 2) & 7, m = (t >> 5) & 511, n = (t >> 14) & 511;
        const float* W = P.w[which] + (size_t)m * 512 + lane;
        const float* X = P.in[which] + (size_t)b * 262144 + n + (size_t)lane * 512;
        float wr[16], xr[16];
#pragma unroll
        for (int i = 0; i < 16; i++) {        // independent loads, MLP=32
            wr[i] = W[i * 32];
            xr[i] = X[(size_t)i * 32 * 512];
        }
        double s0 = 0.0, s1 = 0.0, s2 = 0.0, s3 = 0.0;
#pragma unroll
        for (int i = 0; i < 16; i += 4) {     // 4 independent fp64 chains
            s0 += (double)wr[i + 0] * (double)xr[i + 0];
            s1 += (double)wr[i + 1] * (double)xr[i + 1];
            s2 += (double)wr[i + 2] * (double)xr[i + 2];
            s3 += (double)wr[i + 3] * (double)xr[i + 3];
        }
        double s = (s0 + s1) + (s2 + s3);
#pragma unroll
        for (int o = 16; o; o >>= 1) s += __shfl_down_sync(0xffffffffu, s, o);
        if (lane == 0) {
            const double inv = (double)P.g[which][m] / sqrt((double)P.vr[which][m] + 1e-5);
            const double bn = s * inv + ((double)P.be[which][m] - (double)P.mn[which][m] * inv);
            P.out[which][((size_t)b * 512 + m) * 512 + n] = (bn >= 2.0) ? (uint8_t)1 : (uint8_t)0;
        }
    }
}

__global__ __launch_bounds__(256) void fixup_proj(const float* __restrict__ pw,
                                                  const bf16* __restrict__ sT, float* __restrict__ out,
                                                  const float* __restrict__ g, const float* __restrict__ be,
                                                  const float* __restrict__ mn, const float* __restrict__ vr) {
    const int cnt0 = g_cnt[1];
    const int cnt = cnt0 < FIXCAP ? cnt0 : FIXCAP;
    const int lane = threadIdx.x & 31;
    const int warp = (blockIdx.x * blockDim.x + threadIdx.x) >> 5;
    const int nwarps = (gridDim.x * blockDim.x) >> 5;
    for (int e = warp; e < cnt; e += nwarps) {
        const uint32_t t = g_fix[1][e];
        const int b = (t >> 2) & 7, m = (t >> 5) & 511, n = (t >> 14) & 511;
        const float* W = pw + (size_t)m * 512 + lane;
        const bf16* S = sT + ((size_t)b * 512 + n) * 512 + lane;
        float wr[16], xr[16];
#pragma unroll
        for (int i = 0; i < 16; i++) {
            wr[i] = W[i * 32];
            xr[i] = __bfloat162float(S[i * 32]);
        }
        double s0 = 0.0, s1 = 0.0, s2 = 0.0, s3 = 0.0;
#pragma unroll
        for (int i = 0; i < 16; i += 4) {
            s0 += (double)wr[i + 0] * (double)xr[i + 0];
            s1 += (double)wr[i + 1] * (double)xr[i + 1];
            s2 += (double)wr[i + 2] * (double)xr[i + 2];
            s3 += (double)wr[i + 3] * (double)xr[i + 3];
        }
        double s = (s0 + s1) + (s2 + s3);
#pragma unroll
        for (int o = 16; o; o >>= 1) s += __shfl_down_sync(0xffffffffu, s, o);
        if (lane == 0) {
            const double inv = (double)g[m] / sqrt((double)vr[m] + 1e-5);
            const double bn = s * inv + ((double)be[m] - (double)mn[m] * inv);
            out[((size_t)b * 512 + m) * 512 + n] = (bn >= 2.0) ? 1.0f : 0.0f;
        }
    }
}

// ---------------- spiking attention: o = Q (K^T V), exact int math ----------------
__global__ __launch_bounds__(512)
void attn_lif(const uint8_t* __restrict__ q, const uint8_t* __restrict__ k,
              const uint8_t* __restrict__ v, bf16* __restrict__ sT) {
    __shared__ uint32_t ks[32 * 133];
    __shared__ uint32_t vs[32 * 133];
    __shared__ int M[32][33];

    const int tid = threadIdx.x;
    const int tb = blockIdx.x >> 4;
    const int h = blockIdx.x & 15;
    const size_t base = ((size_t)tb * 512 + h * 32) * 512;

    const uint32_t* ksrc = (const uint32_t*)(k + base);
    const uint32_t* vsrc = (const uint32_t*)(v + base);
    for (int f = tid; f < 2 * 4096; f += 512) {
        const int r = (f >> 7) & 31, w = f & 127;
        if (f < 4096) ks[r * 133 + w] = ksrc[r * 128 + w];
        else          vs[r * 133 + w] = vsrc[r * 128 + w];
    }
    __syncthreads();

    if (tid < 256) {
        const int dp = tid >> 3, dd0 = (tid & 7) * 4;
        unsigned a0 = 0, a1 = 0, a2 = 0, a3 = 0;
        const uint32_t* kr = &ks[dp * 133];
        const uint32_t* v0 = &vs[(dd0 + 0) * 133];
        const uint32_t* v1 = &vs[(dd0 + 1) * 133];
        const uint32_t* v2 = &vs[(dd0 + 2) * 133];
        const uint32_t* v3 = &vs[(dd0 + 3) * 133];
#pragma unroll 8
        for (int w = 0; w < 128; w++) {
            const uint32_t kw = kr[w];
            a0 = __dp4a(kw, v0[w], a0);
            a1 = __dp4a(kw, v1[w], a1);
            a2 = __dp4a(kw, v2[w], a2);
            a3 = __dp4a(kw, v3[w], a3);
        }
        M[dp][dd0 + 0] = (int)a0; M[dp][dd0 + 1] = (int)a1;
        M[dp][dd0 + 2] = (int)a2; M[dp][dd0 + 3] = (int)a3;
    }
    __syncthreads();

    const int n = tid;
    int oacc[32];
#pragma unroll
    for (int d = 0; d < 32; d++) oacc[d] = 0;
#pragma unroll 4
    for (int dp = 0; dp < 32; dp++) {
        if (q[base + (size_t)dp * 512 + n]) {
#pragma unroll
            for (int d = 0; d < 32; d++) oacc[d] += M[dp][d];
        }
    }
    // LIF(o*0.25/2) == (o_int >= 8). Write spikes^T as bf16 {0,1} at [b][n][c].
    uint32_t* dst = (uint32_t*)(sT + ((size_t)tb * 512 + n) * 512 + h * 32);
#pragma unroll
    for (int g = 0; g < 16; g++) {
        const uint32_t lo = (oacc[2 * g] >= 8) ? 0x3F80u : 0u;
        const uint32_t hi = (oacc[2 * g + 1] >= 8) ? 0x3F80u : 0u;
        dst[g] = lo | (hi << 16);
    }
}

// ---------------------------------------------------------------------------
extern "C" void kernel_launch(void* const* d_in, const int* in_sizes, int n_in,
                              void* d_out, int out_size) {
    (void)in_sizes; (void)n_in; (void)out_size;
    const float* x = (const float*)d_in[0];
    const float* y = (const float*)d_in[1];
    const float* w[4]  = {(const float*)d_in[2], (const float*)d_in[7], (const float*)d_in[12], (const float*)d_in[17]};
    const float* bg[4] = {(const float*)d_in[3], (const float*)d_in[8], (const float*)d_in[13], (const float*)d_in[18]};
    const float* bb[4] = {(const float*)d_in[4], (const float*)d_in[9], (const float*)d_in[14], (const float*)d_in[19]};
    const float* bm[4] = {(const float*)d_in[5], (const float*)d_in[10], (const float*)d_in[15], (const float*)d_in[20]};
    const float* bv[4] = {(const float*)d_in[6], (const float*)d_in[11], (const float*)d_in[16], (const float*)d_in[21]};

    bf16 *wsp, *xT, *yT, *sT;
    uint8_t *gq, *gk, *gv;
    cudaGetSymbolAddress((void**)&wsp, g_wsp);
    cudaGetSymbolAddress((void**)&xT, g_xT);
    cudaGetSymbolAddress((void**)&yT, g_yT);
    cudaGetSymbolAddress((void**)&sT, g_sT);
    cudaGetSymbolAddress((void**)&gq, g_q);
    cudaGetSymbolAddress((void**)&gk, g_k);
    cudaGetSymbolAddress((void**)&gv, g_v);

    cudaFuncSetAttribute(gemm_qkv, cudaFuncAttributeMaxDynamicSharedMemorySize, 131072);
    cudaFuncSetAttribute(gemm_proj, cudaFuncAttributeMaxDynamicSharedMemorySize, 98304);

    prep_split4<<<dim3(64, 4), 256>>>(w[0], w[1], w[2], w[3], wsp);
    prep_xyT<<<dim3(16, 16, 16), 256>>>(x, y, xT, yT);

    QKVp P;
    uint8_t* outs[3] = {gq, gk, gv};
    for (int g = 0; g < 3; g++) {
        P.A0[g] = wsp + (size_t)(g * 2 + 0) * WSZ;
        P.A1[g] = wsp + (size_t)(g * 2 + 1) * WSZ;
        P.B0[g] = (g == 0) ? xT : yT;
        P.B1[g] = ((g == 0) ? xT : yT) + (size_t)XSZ;
        P.out[g] = outs[g];
        P.gam[g] = bg[g]; P.bet[g] = bb[g]; P.mean[g] = bm[g]; P.var[g] = bv[g];
    }
    gemm_qkv<<<dim3(4, 4, 24), 256, 131072>>>(P);

    FixQ F;
    F.in[0] = x; F.in[1] = y; F.in[2] = y;
    for (int g = 0; g < 3; g++) {
        F.w[g] = w[g]; F.g[g] = bg[g]; F.be[g] = bb[g]; F.mn[g] = bm[g]; F.vr[g] = bv[g];
        F.out[g] = outs[g];
    }
    fixup_qkv<<<512, 256>>>(F);

    attn_lif<<<128, 512>>>(gq, gk, gv, sT);

    gemm_proj<<<dim3(4, 4, 8), 256, 98304>>>(wsp + 6 * (size_t)WSZ, wsp + 7 * (size_t)WSZ,
                                             sT, (float*)d_out, bg[3], bb[3], bm[3], bv[3]);

    fixup_proj<<<512, 256>>>(w[3], sT, (float*)d_out, bg[3], bb[3], bm[3], bv[3]);
}

// round 11
// speedup vs baseline: 1.2372x; 1.0156x over previous
#include <cuda_runtime.h>
#include <cuda_bf16.h>
#include <cstdint>

typedef __nv_bfloat16 bf16;

#define WSZ (512*512)
#define XSZ (8*512*512)
#define FIXCAP (1<<20)
#define FLAGWIN 5e-4f   // ~12-sigma of split-GEMM noise in bn units

// ---------------- device scratch ----------------
__device__ bf16     g_wsp[4][2][WSZ];   // weight splits (2 levels)
__device__ bf16     g_xT[2][XSZ];       // x^T splits [b][n][c]
__device__ bf16     g_yT[2][XSZ];       // y^T splits
__device__ uint8_t  g_q[XSZ], g_k[XSZ], g_v[XSZ];
__device__ bf16     g_sT[XSZ];          // attn spikes^T bf16 [b][n][c]
__device__ int      g_cnt[2];
__device__ uint32_t g_fix[2][FIXCAP];

// ---------------- PTX helpers (arch-generic, sm_80+) ----------------
__device__ __forceinline__ uint32_t smem_u32(const void* p) {
    uint32_t a;
    asm("{ .reg .u64 t; cvta.to.shared.u64 t, %1; cvt.u32.u64 %0, t; }" : "=r"(a) : "l"(p));
    return a;
}
__device__ __forceinline__ void cp16(uint32_t dst, const void* src) {
    asm volatile("cp.async.cg.shared.global [%0], [%1], 16;" :: "r"(dst), "l"(src) : "memory");
}
__device__ __forceinline__ void cp_commit() { asm volatile("cp.async.commit_group;" ::: "memory"); }
template<int N> __device__ __forceinline__ void cp_wait() {
    asm volatile("cp.async.wait_group %0;" :: "n"(N) : "memory");
}
__device__ __forceinline__ void ldmx4(uint32_t& r0, uint32_t& r1, uint32_t& r2, uint32_t& r3, uint32_t a) {
    asm volatile("ldmatrix.sync.aligned.m8n8.x4.shared.b16 {%0,%1,%2,%3}, [%4];"
                 : "=r"(r0), "=r"(r1), "=r"(r2), "=r"(r3) : "r"(a));
}
__device__ __forceinline__ void mma_bf16(float& c0, float& c1, float& c2, float& c3,
                                         uint32_t a0, uint32_t a1, uint32_t a2, uint32_t a3,
                                         uint32_t b0, uint32_t b1) {
    asm volatile("mma.sync.aligned.m16n8k16.row.col.f32.bf16.bf16.f32 "
                 "{%0,%1,%2,%3}, {%4,%5,%6,%7}, {%8,%9}, {%0,%1,%2,%3};"
                 : "+f"(c0), "+f"(c1), "+f"(c2), "+f"(c3)
                 : "r"(a0), "r"(a1), "r"(a2), "r"(a3), "r"(b0), "r"(b1));
}

// 2-way bf16 split (truncation): w ≈ h + l, residual ~2^-16 relative
__device__ __forceinline__ void split2(float w, bf16& h, bf16& l) {
    h = __float2bfloat16_rz(w);
    l = __float2bfloat16_rz(w - __bfloat162float(h));
}

// ---------------- prep kernels ----------------
__global__ void prep_split4(const float* __restrict__ w0, const float* __restrict__ w1,
                            const float* __restrict__ w2, const float* __restrict__ w3,
                            bf16* __restrict__ dst) {
    if (blockIdx.x == 0 && blockIdx.y == 0 && threadIdx.x == 0) { g_cnt[0] = 0; g_cnt[1] = 0; }
    const float* ws[4] = {w0, w1, w2, w3};
    const int wi = blockIdx.y;
    const float* w = ws[wi];
    bf16* h = dst + (size_t)(wi * 2 + 0) * WSZ;
    bf16* l = dst + (size_t)(wi * 2 + 1) * WSZ;
    for (int i = blockIdx.x * 256 + threadIdx.x; i < WSZ; i += gridDim.x * 256) {
        bf16 a, b;
        split2(w[i], a, b);
        h[i] = a; l[i] = b;
    }
}

// transpose [b][c][n] -> [b][n][c] with 2-way split; z<8: x->xT, z>=8: y->yT
__global__ void prep_xyT(const float* __restrict__ x, const float* __restrict__ y,
                         bf16* __restrict__ xT, bf16* __restrict__ yT) {
    __shared__ float t[32][33];
    const int z = blockIdx.z;
    const int b = z & 7;
    const float* src0 = (z < 8) ? x : y;
    bf16* d0 = (z < 8) ? xT : yT;
    const int c0 = blockIdx.y * 32, n0 = blockIdx.x * 32;
    const int r = threadIdx.x >> 5, j = threadIdx.x & 31;
    const float* src = src0 + ((size_t)b * 512 + c0) * 512 + n0;
#pragma unroll
    for (int i = r; i < 32; i += 8) t[i][j] = src[(size_t)i * 512 + j];
    __syncthreads();
    const size_t dst = ((size_t)b * 512 + n0) * 512 + c0;
#pragma unroll
    for (int i = r; i < 32; i += 8) {
        bf16 a, bb;
        split2(t[j][i], a, bb);
        d0[0 * (size_t)XSZ + dst + (size_t)i * 512 + j] = a;
        d0[1 * (size_t)XSZ + dst + (size_t)i * 512 + j] = bb;
    }
}

// ---------------- bf16 mma GEMM + BN + LIF (+ borderline flagging) ----------------
// D = A0*B0 + A0*B1 + A1*B0 (NB=2)  or  A0*B0 + A1*B0 (NB=1)
// 128x128 tile, BK=64, 8 stages, double-buffered cp.async, 256 threads (2x4 warps).
template<int NB, bool OUT_U8>
__device__ __forceinline__ void gemm_body(const bf16* __restrict__ A0, const bf16* __restrict__ A1,
                                          const bf16* __restrict__ B0, const bf16* __restrict__ B1,
                                          void* Out,
                                          const float* __restrict__ gam, const float* __restrict__ bet,
                                          const float* __restrict__ mean, const float* __restrict__ var,
                                          int bz, int stage, int which, char* sm) {
    const int NT = 2 + NB;                 // tiles per stage
    const int tid = threadIdx.x;
    const int lane = tid & 31, wid = tid >> 5;
    const int warp_m = wid & 1, warp_n = wid >> 1;
    const int row0 = blockIdx.y * 128, col0 = blockIdx.x * 128;
    const uint32_t sbase = smem_u32(sm);

    float acc[4][4][4];
#pragma unroll
    for (int i = 0; i < 4; i++)
#pragma unroll
        for (int j = 0; j < 4; j++)
#pragma unroll
            for (int q = 0; q < 4; q++) acc[i][j][q] = 0.0f;

    const bf16* srcs[4];
    srcs[0] = A0 + (size_t)row0 * 512;
    srcs[1] = A1 + (size_t)row0 * 512;
    srcs[2] = B0 + ((size_t)bz * 512 + col0) * 512;
    if (NB == 2) srcs[3] = B1 + ((size_t)bz * 512 + col0) * 512;

    // stage = NT tiles of [128][64] bf16; tile chunk (r, c): 16B at row r, chunk c^(r&7)
    auto issue = [&](int kt, int stg) {
        const uint32_t sb = sbase + stg * NT * 16384;
#pragma unroll
        for (int t = 0; t < NT; t++) {
            const bf16* base = srcs[t] + (kt << 6);
#pragma unroll
            for (int i = 0; i < 4; i++) {
                const int idx = tid + i * 256;
                const int r = idx >> 3, c = idx & 7;
                const uint32_t off = r * 128 + ((c ^ (r & 7)) << 4);
                cp16(sb + t * 16384 + off, base + (size_t)r * 512 + c * 8);
            }
        }
        cp_commit();
    };

    auto ldA = [&](uint32_t Af[4][4], uint32_t sA, int ks) {
#pragma unroll
        for (int tm = 0; tm < 4; tm++) {
            const int r = warp_m * 64 + tm * 16 + (lane & 15);
            const int ch = ks * 2 + (lane >> 4);
            ldmx4(Af[tm][0], Af[tm][1], Af[tm][2], Af[tm][3],
                  sA + r * 128 + ((ch ^ (r & 7)) << 4));
        }
    };
    auto ldB = [&](uint32_t Bf[2][4], uint32_t sB, int ks) {
#pragma unroll
        for (int tp = 0; tp < 2; tp++) {
            const int r = warp_n * 32 + tp * 16 + (lane & 7) + ((lane & 16) >> 1);
            const int ch = ks * 2 + ((lane >> 3) & 1);
            ldmx4(Bf[tp][0], Bf[tp][1], Bf[tp][2], Bf[tp][3],
                  sB + r * 128 + ((ch ^ (r & 7)) << 4));
        }
    };
    auto pass = [&](uint32_t Af[4][4], uint32_t Bf[2][4]) {
#pragma unroll
        for (int tm = 0; tm < 4; tm++)
#pragma unroll
            for (int tn = 0; tn < 4; tn++)
                mma_bf16(acc[tm][tn][0], acc[tm][tn][1], acc[tm][tn][2], acc[tm][tn][3],
                         Af[tm][0], Af[tm][1], Af[tm][2], Af[tm][3],
                         Bf[tn >> 1][(tn & 1) * 2], Bf[tn >> 1][(tn & 1) * 2 + 1]);
    };

    auto compute = [&](int stg) {
        const uint32_t sb = sbase + stg * NT * 16384;
#pragma unroll
        for (int ks = 0; ks < 4; ks++) {
            uint32_t Af0[4][4], Af1[4][4], Bf0[2][4];
            ldA(Af0, sb, ks);
            ldB(Bf0, sb + 2 * 16384, ks);
            ldA(Af1, sb + 16384, ks);
            if (NB == 2) {
                uint32_t Bf1[2][4];
                ldB(Bf1, sb + 3 * 16384, ks);
                pass(Af0, Bf0);
                pass(Af0, Bf1);
                pass(Af1, Bf0);
            } else {
                pass(Af0, Bf0);
                pass(Af1, Bf0);
            }
        }
    };

    issue(0, 0);
    for (int kt = 0; kt < 8; kt++) {
        if (kt + 1 < 8) { issue(kt + 1, (kt + 1) & 1); cp_wait<1>(); }
        else cp_wait<0>();
        __syncthreads();
        compute(kt & 1);
        __syncthreads();
    }

    // ---- epilogue: BN + LIF; flag borderline values for exact fp64 fixup ----
    const int r0l = lane >> 2, c0l = (lane & 3) * 2;
#pragma unroll
    for (int tm = 0; tm < 4; tm++) {
#pragma unroll
        for (int half = 0; half < 2; half++) {
            const int m = row0 + warp_m * 64 + tm * 16 + r0l + half * 8;
            const float invv = gam[m] / sqrtf(var[m] + 1e-5f);
            const float offv = bet[m] - mean[m] * invv;
            const size_t rowbase = ((size_t)bz * 512 + m) * 512 + col0 + warp_n * 32;
#pragma unroll
            for (int tn = 0; tn < 4; tn++) {
                const float bn0 = acc[tm][tn][half * 2 + 0] * invv + offv;
                const float bn1 = acc[tm][tn][half * 2 + 1] * invv + offv;
                const bool s0 = (bn0 >= 2.0f);
                const bool s1 = (bn1 >= 2.0f);
                const int ncol = col0 + warp_n * 32 + tn * 8 + c0l;
                if (fabsf(bn0 - 2.0f) < FLAGWIN) {
                    int ix = atomicAdd(&g_cnt[stage], 1);
                    if (ix < FIXCAP)
                        g_fix[stage][ix] = (uint32_t)which | ((uint32_t)bz << 2) |
                                           ((uint32_t)m << 5) | ((uint32_t)ncol << 14);
                }
                if (fabsf(bn1 - 2.0f) < FLAGWIN) {
                    int ix = atomicAdd(&g_cnt[stage], 1);
                    if (ix < FIXCAP)
                        g_fix[stage][ix] = (uint32_t)which | ((uint32_t)bz << 2) |
                                           ((uint32_t)m << 5) | ((uint32_t)(ncol + 1) << 14);
                }
                const size_t o = rowbase + tn * 8 + c0l;
                if (OUT_U8) {
                    *(unsigned short*)((uint8_t*)Out + o) =
                        (unsigned short)((s0 ? 1u : 0u) | ((s1 ? 1u : 0u) << 8));
                } else {
                    *(float2*)((float*)Out + o) = make_float2(s0 ? 1.f : 0.f, s1 ? 1.f : 0.f);
                }
            }
        }
    }
}

struct QKVp {
    const bf16 *A0[3], *A1[3], *B0[3], *B1[3];
    uint8_t* out[3];
    const float *gam[3], *bet[3], *mean[3], *var[3];
};

__global__ __launch_bounds__(256, 1) void gemm_qkv(QKVp P) {
    extern __shared__ char sm[];
    const int which = blockIdx.z >> 3;
    const int bz = blockIdx.z & 7;
    gemm_body<2, true>(P.A0[which], P.A1[which], P.B0[which], P.B1[which], P.out[which],
                       P.gam[which], P.bet[which], P.mean[which], P.var[which],
                       bz, 0, which, sm);
}

__global__ __launch_bounds__(256, 1) void gemm_proj(const bf16* A0, const bf16* A1,
                                                    const bf16* B0, float* Out,
                                                    const float* g, const float* b,
                                                    const float* m, const float* v) {
    extern __shared__ char sm[];
    gemm_body<1, false>(A0, A1, B0, B0, Out, g, b, m, v, blockIdx.z, 1, 0, sm);
}

// ---------------- exact fp64 fixup of borderline spikes ----------------
// ONE BLOCK PER ENTRY: 256 threads x 2 channels -> one memory round + 2-level reduce.
struct FixQ {
    const float* in[3];    // original [b][c][n]
    const float* w[3];
    const float *g[3], *be[3], *mn[3], *vr[3];
    uint8_t* out[3];
};

__global__ __launch_bounds__(256) void fixup_qkv(FixQ P) {
    __shared__ double red[8];
    const int cnt0 = g_cnt[0];
    const int cnt = cnt0 < FIXCAP ? cnt0 : FIXCAP;
    const int tid = threadIdx.x, lane = tid & 31, wid = tid >> 5;
    for (int e = blockIdx.x; e < cnt; e += gridDim.x) {
        const uint32_t t = g_fix[0][e];
        const int which = t & 3, b = (t >> 2) & 7, m = (t >> 5) & 511, n = (t >> 14) & 511;
        const float* W = P.w[which] + (size_t)m * 512;
        const float* X = P.in[which] + (size_t)b * 262144 + n;
        // channels tid and tid+256 (independent loads, full-block MLP)
        const float w0 = W[tid],        x0 = X[(size_t)tid * 512];
        const float w1 = W[tid + 256],  x1 = X[(size_t)(tid + 256) * 512];
        double s = (double)w0 * (double)x0 + (double)w1 * (double)x1;
#pragma unroll
        for (int o = 16; o; o >>= 1) s += __shfl_down_sync(0xffffffffu, s, o);
        if (lane == 0) red[wid] = s;
        __syncthreads();
        if (tid == 0) {
            double sum = red[0];
#pragma unroll
            for (int i = 1; i < 8; i++) sum += red[i];
            const double inv = (double)P.g[which][m] / sqrt((double)P.vr[which][m] + 1e-5);
            const double bn = sum * inv + ((double)P.be[which][m] - (double)P.mn[which][m] * inv);
            P.out[which][((size_t)b * 512 + m) * 512 + n] = (bn >= 2.0) ? (uint8_t)1 : (uint8_t)0;
        }
        __syncthreads();
    }
}

__global__ __launch_bounds__(256) void fixup_proj(const float* __restrict__ pw,
                                                  const bf16* __restrict__ sT, float* __restrict__ out,
                                                  const float* __restrict__ g, const float* __restrict__ be,
                                                  const float* __restrict__ mn, const float* __restrict__ vr) {
    __shared__ double red[8];
    const int cnt0 = g_cnt[1];
    const int cnt = cnt0 < FIXCAP ? cnt0 : FIXCAP;
    const int tid = threadIdx.x, lane = tid & 31, wid = tid >> 5;
    for (int e = blockIdx.x; e < cnt; e += gridDim.x) {
        const uint32_t t = g_fix[1][e];
        const int b = (t >> 2) & 7, m = (t >> 5) & 511, n = (t >> 14) & 511;
        const float* W = pw + (size_t)m * 512;
        const bf16* S = sT + ((size_t)b * 512 + n) * 512;
        const float w0 = W[tid],       x0 = __bfloat162float(S[tid]);
        const float w1 = W[tid + 256], x1 = __bfloat162float(S[tid + 256]);
        double s = (double)w0 * (double)x0 + (double)w1 * (double)x1;
#pragma unroll
        for (int o = 16; o; o >>= 1) s += __shfl_down_sync(0xffffffffu, s, o);
        if (lane == 0) red[wid] = s;
        __syncthreads();
        if (tid == 0) {
            double sum = red[0];
#pragma unroll
            for (int i = 1; i < 8; i++) sum += red[i];
            const double inv = (double)g[m] / sqrt((double)vr[m] + 1e-5);
            const double bn = sum * inv + ((double)be[m] - (double)mn[m] * inv);
            out[((size_t)b * 512 + m) * 512 + n] = (bn >= 2.0) ? 1.0f : 0.0f;
        }
        __syncthreads();
    }
}

// ---------------- spiking attention: o = Q (K^T V), exact int math ----------------
__global__ __launch_bounds__(512)
void attn_lif(const uint8_t* __restrict__ q, const uint8_t* __restrict__ k,
              const uint8_t* __restrict__ v, bf16* __restrict__ sT) {
    __shared__ uint32_t ks[32 * 133];
    __shared__ uint32_t vs[32 * 133];
    __shared__ int M[32][33];

    const int tid = threadIdx.x;
    const int tb = blockIdx.x >> 4;
    const int h = blockIdx.x & 15;
    const size_t base = ((size_t)tb * 512 + h * 32) * 512;

    const uint32_t* ksrc = (const uint32_t*)(k + base);
    const uint32_t* vsrc = (const uint32_t*)(v + base);
    for (int f = tid; f < 2 * 4096; f += 512) {
        const int r = (f >> 7) & 31, w = f & 127;
        if (f < 4096) ks[r * 133 + w] = ksrc[r * 128 + w];
        else          vs[r * 133 + w] = vsrc[r * 128 + w];
    }
    __syncthreads();

    if (tid < 256) {
        const int dp = tid >> 3, dd0 = (tid & 7) * 4;
        unsigned a0 = 0, a1 = 0, a2 = 0, a3 = 0;
        const uint32_t* kr = &ks[dp * 133];
        const uint32_t* v0 = &vs[(dd0 + 0) * 133];
        const uint32_t* v1 = &vs[(dd0 + 1) * 133];
        const uint32_t* v2 = &vs[(dd0 + 2) * 133];
        const uint32_t* v3 = &vs[(dd0 + 3) * 133];
#pragma unroll 8
        for (int w = 0; w < 128; w++) {
            const uint32_t kw = kr[w];
            a0 = __dp4a(kw, v0[w], a0);
            a1 = __dp4a(kw, v1[w], a1);
            a2 = __dp4a(kw, v2[w], a2);
            a3 = __dp4a(kw, v3[w], a3);
        }
        M[dp][dd0 + 0] = (int)a0; M[dp][dd0 + 1] = (int)a1;
        M[dp][dd0 + 2] = (int)a2; M[dp][dd0 + 3] = (int)a3;
    }
    __syncthreads();

    const int n = tid;
    int oacc[32];
#pragma unroll
    for (int d = 0; d < 32; d++) oacc[d] = 0;
#pragma unroll 4
    for (int dp = 0; dp < 32; dp++) {
        if (q[base + (size_t)dp * 512 + n]) {
#pragma unroll
            for (int d = 0; d < 32; d++) oacc[d] += M[dp][d];
        }
    }
    // LIF(o*0.25/2) == (o_int >= 8). Write spikes^T as bf16 {0,1} at [b][n][c].
    uint32_t* dst = (uint32_t*)(sT + ((size_t)tb * 512 + n) * 512 + h * 32);
#pragma unroll
    for (int g = 0; g < 16; g++) {
        const uint32_t lo = (oacc[2 * g] >= 8) ? 0x3F80u : 0u;
        const uint32_t hi = (oacc[2 * g + 1] >= 8) ? 0x3F80u : 0u;
        dst[g] = lo | (hi << 16);
    }
}

// ---------------------------------------------------------------------------
extern "C" void kernel_launch(void* const* d_in, const int* in_sizes, int n_in,
                              void* d_out, int out_size) {
    (void)in_sizes; (void)n_in; (void)out_size;
    const float* x = (const float*)d_in[0];
    const float* y = (const float*)d_in[1];
    const float* w[4]  = {(const float*)d_in[2], (const float*)d_in[7], (const float*)d_in[12], (const float*)d_in[17]};
    const float* bg[4] = {(const float*)d_in[3], (const float*)d_in[8], (const float*)d_in[13], (const float*)d_in[18]};
    const float* bb[4] = {(const float*)d_in[4], (const float*)d_in[9], (const float*)d_in[14], (const float*)d_in[19]};
    const float* bm[4] = {(const float*)d_in[5], (const float*)d_in[10], (const float*)d_in[15], (const float*)d_in[20]};
    const float* bv[4] = {(const float*)d_in[6], (const float*)d_in[11], (const float*)d_in[16], (const float*)d_in[21]};

    bf16 *wsp, *xT, *yT, *sT;
    uint8_t *gq, *gk, *gv;
    cudaGetSymbolAddress((void**)&wsp, g_wsp);
    cudaGetSymbolAddress((void**)&xT, g_xT);
    cudaGetSymbolAddress((void**)&yT, g_yT);
    cudaGetSymbolAddress((void**)&sT, g_sT);
    cudaGetSymbolAddress((void**)&gq, g_q);
    cudaGetSymbolAddress((void**)&gk, g_k);
    cudaGetSymbolAddress((void**)&gv, g_v);

    cudaFuncSetAttribute(gemm_qkv, cudaFuncAttributeMaxDynamicSharedMemorySize, 131072);
    cudaFuncSetAttribute(gemm_proj, cudaFuncAttributeMaxDynamicSharedMemorySize, 98304);

    prep_split4<<<dim3(64, 4), 256>>>(w[0], w[1], w[2], w[3], wsp);
    prep_xyT<<<dim3(16, 16, 16), 256>>>(x, y, xT, yT);

    QKVp P;
    uint8_t* outs[3] = {gq, gk, gv};
    for (int g = 0; g < 3; g++) {
        P.A0[g] = wsp + (size_t)(g * 2 + 0) * WSZ;
        P.A1[g] = wsp + (size_t)(g * 2 + 1) * WSZ;
        P.B0[g] = (g == 0) ? xT : yT;
        P.B1[g] = ((g == 0) ? xT : yT) + (size_t)XSZ;
        P.out[g] = outs[g];
        P.gam[g] = bg[g]; P.bet[g] = bb[g]; P.mean[g] = bm[g]; P.var[g] = bv[g];
    }
    gemm_qkv<<<dim3(4, 4, 24), 256, 131072>>>(P);

    FixQ F;
    F.in[0] = x; F.in[1] = y; F.in[2] = y;
    for (int g = 0; g < 3; g++) {
        F.w[g] = w[g]; F.g[g] = bg[g]; F.be[g] = bb[g]; F.mn[g] = bm[g]; F.vr[g] = bv[g];
        F.out[g] = outs[g];
    }
    fixup_qkv<<<1024, 256>>>(F);

    attn_lif<<<128, 512>>>(gq, gk, gv, sT);

    gemm_proj<<<dim3(4, 4, 8), 256, 98304>>>(wsp + 6 * (size_t)WSZ, wsp + 7 * (size_t)WSZ,
                                             sT, (float*)d_out, bg[3], bb[3], bm[3], bv[3]);

    fixup_proj<<<1024, 256>>>(w[3], sT, (float*)d_out, bg[3], bb[3], bm[3], bv[3]);
}